// round 17
// baseline (speedup 1.0000x reference)
#include <cuda_runtime.h>
#include <cuda_fp16.h>
#include <math.h>
#include <stdint.h>

#define BATCH 2048
#define HDIM  1024
#define G3    3072
#define NMSG  4096

// ---------------- scratch (static device globals; no allocation) ----------------
__device__ __align__(16) __half g_msgAll[6LL * BATCH * NMSG];  // all sender projections
__device__ __align__(16) __half g_giAll[13LL * BATCH * G3];    // fp16 staging
__device__ __align__(16) __half g_HinR[(long)BATCH * HDIM];    // fp16 H_in
__device__ __align__(16) __half g_Hv1[(long)BATCH * HDIM];     // ping
__device__ __align__(16) __half g_Hv2[(long)BATCH * HDIM];     // pong
__device__ __align__(16) __half g_Xpad[13LL * BATCH * 32];
__device__ __align__(16) __half g_Wx32[3LL * G3 * 32];
__device__ __align__(16) __half g_Whh3R[3LL * G3 * HDIM];      // [c|l|r]
__device__ __align__(16) __half g_WmsgR[(long)NMSG * HDIM];
__device__ __align__(16) __half g_WoutR[512L * HDIM];          // [Wmu;Wstd]
__device__ float g_bout[512];                                   // [bmu;bstd]

__device__ __forceinline__ float sigmoidf(float x) { return 1.f / (1.f + expf(-x)); }
__device__ __forceinline__ float softplusf(float x) {
    return (x > 20.f) ? x : log1pf(expf(x));
}

// ---------------- packing (emit fp16 operands) ----------------
__global__ void pack_xpad(const float* __restrict__ X, const int* __restrict__ adj,
                          __half* __restrict__ Xp) {
    int idx = blockIdx.x * blockDim.x + threadIdx.x;
    if (idx >= 13 * BATCH * 32) return;
    int slot = idx / (BATCH * 32);
    int rem  = idx - slot * (BATCH * 32);
    int b = rem >> 5, k = rem & 31;
    float v = 0.f;
    if (slot < 6) {
        int node = slot + 1;
        if (k < 27) v = X[(long)b * 189 + node * 27 + k];
    } else if (slot < 12) {
        int node = slot - 5;
        if (k < 27 && adj[(long)b * 49 + node * 8] > 0)
            v = X[(long)b * 189 + node * 27 + k];
    } else {
        if (k < 23) v = X[(long)b * 189 + k];
    }
    Xp[idx] = __float2half_rn(v);
}

__global__ void pack_wx32(const float* __restrict__ W, __half* __restrict__ P, int K) {
    int idx = blockIdx.x * blockDim.x + threadIdx.x;
    if (idx >= G3 * 32) return;
    int j = idx >> 5, k = idx & 31;
    P[idx] = __float2half_rn((k < K) ? W[j * K + k] : 0.f);
}

__global__ void pack_msgw(const float* __restrict__ Wg, const float* __restrict__ Wm,
                          __half* __restrict__ P) {
    int idx = blockIdx.x * blockDim.x + threadIdx.x;
    int j = idx >> 10, k = idx & 1023;
    float v;
    if (j < 1024)       v = Wg[j * 2048 + k];
    else if (j < 2048)  v = Wg[(j - 1024) * 2048 + 1024 + k];
    else if (j < 3072)  v = Wm[(j - 2048) * 2048 + k];
    else                v = Wm[(j - 3072) * 2048 + 1024 + k];
    P[idx] = __float2half_rn(v);
}

__global__ void half_copy3(const float* __restrict__ a, const float* __restrict__ b,
                           const float* __restrict__ c, __half* __restrict__ out,
                           int n) {
    int idx = blockIdx.x * blockDim.x + threadIdx.x;
    if (idx >= 3 * n) return;
    int seg = idx / n, r = idx - seg * n;
    const float* src = (seg == 0) ? a : (seg == 1) ? b : c;
    out[idx] = __float2half_rn(src[r]);
}

__global__ void half_copy2(const float* __restrict__ a, const float* __restrict__ b,
                           __half* __restrict__ out, int n) {
    int idx = blockIdx.x * blockDim.x + threadIdx.x;
    if (idx >= 2 * n) return;
    out[idx] = __float2half_rn(idx < n ? a[idx] : b[idx - n]);
}

// v=6 GRU1: gh = bias (H_in = 0), hp = 0
__global__ __launch_bounds__(256) void gru_combine_bias(
    const __half* __restrict__ gi, const float* __restrict__ bhh,
    __half* __restrict__ hoR)
{
    int idx = blockIdx.x * 256 + threadIdx.x;
    int b = idx >> 10, h = idx & 1023;
    long base = (long)b * G3 + h;
    float ir = __half2float(gi[base]);
    float iz = __half2float(gi[base + 1024]);
    float in_ = __half2float(gi[base + 2048]);
    float hr = bhh[h], hz = bhh[1024 + h], hn = bhh[2048 + h];
    float r = sigmoidf(ir + hr);
    float z = sigmoidf(iz + hz);
    float n = tanhf(in_ + r * hn);
    hoR[idx] = __float2half_rn((1.f - z) * n);
}

// ---------------- lazy gather: H_in[v] = sum over senders S > v ----------------
__global__ __launch_bounds__(256) void msg_gather(
    const __half* __restrict__ msgAll, const int* __restrict__ adj,
    const float* __restrict__ bg, __half* __restrict__ HinR, int v)
{
    int idx = blockIdx.x * 256 + threadIdx.x;    // BATCH*HDIM
    int b = idx >> 10, h = idx & 1023;
    const int* arow = adj + (long)b * 49;
    float bgh = bg[h];
    float acc = 0.f;
    for (int S = v + 1; S <= 6; S++) {
        bool fp = arow[S * 7 + v] > 0;
        bool fs = arow[v * 7 + S] > 0;
        if (fp | fs) {
            const __half* M = msgAll + ((long)(S - 1) * BATCH + b) * NMSG;
            float a = 0.f, m = 0.f;
            if (fp) { a += __half2float(M[h]);        m += __half2float(M[2048 + h]); }
            if (fs) { a += __half2float(M[1024 + h]); m += __half2float(M[3072 + h]); }
            acc += sigmoidf(a + bgh) * m;
        }
    }
    HinR[idx] = __float2half_rn(acc);
}

// ================= fused GRU GEMM: all 3 gates + combine in epilogue =============
// A [2048,1024] fp16; B = Whh [3072,1024] fp16 (rows gate*1024+h).
// CTA: 128 batch rows x 64 hiddens x 3 gates. Grid (16, 16).
// Epilogue: r/z/n combine with gi (fp16, [row][gate*1024+h]), hp (fp16), bias bhh
// (f32, [gate*1024+h]); writes out fp16 [row][h].  out must differ from A/hp-alias
// rules: out != A (hp may equal A; each out element written once after all A reads
// by THIS cta... hp==A is safe because hp[row,h] is read only by the thread that
// writes out[row,h], and out != A/hp buffer).  We always pass out distinct from A.
#define KS 20
#define GG_ASZ (128 * KS * 4)
#define GG_BSZ (192 * KS * 4)
#define GG_SMEM (2 * (GG_ASZ + GG_BSZ))     // 51200 B

__global__ __launch_bounds__(256) void gru_gemm(
    const __half* __restrict__ A, const __half* __restrict__ B,
    const float* __restrict__ bhh, const __half* __restrict__ gi,
    const __half* __restrict__ hp, __half* __restrict__ out)
{
    extern __shared__ char dsm[];
    unsigned (*As)[128][KS] = (unsigned (*)[128][KS])dsm;
    unsigned (*Bs)[192][KS] = (unsigned (*)[192][KS])(dsm + 2 * GG_ASZ);

    const int tid  = threadIdx.x;
    const int lane = tid & 31;
    const int warp = tid >> 5;
    const int wm   = warp >> 1;            // 0..3
    const int wn   = warp & 1;             // 0..1
    const long bm  = (long)blockIdx.y * 128;
    const int  bx  = blockIdx.x;           // hidden block (64 h's)
    const int  K   = 1024;

    float acc[2][3][4][4];
#pragma unroll
    for (int i = 0; i < 2; i++)
#pragma unroll
        for (int g = 0; g < 3; g++)
#pragma unroll
            for (int j = 0; j < 4; j++)
#pragma unroll
                for (int q = 0; q < 4; q++) acc[i][g][j][q] = 0.f;

    // loaders: A 128 rows x 4 chunks (512 uint4); B 192 rows x 4 chunks (768 uint4)
    auto fill = [&](int buf, int koff) {
#pragma unroll
        for (int i = 0; i < 2; i++) {
            int idx = tid + i * 256;           // < 512
            int r = idx >> 2, c = idx & 3;
            *(uint4*)&As[buf][r][c * 4] =
                *(const uint4*)(A + (bm + r) * K + koff + c * 8);
        }
#pragma unroll
        for (int i = 0; i < 3; i++) {
            int idx = tid + i * 256;           // < 768
            int lr = idx >> 2, c = idx & 3;
            long grow = (long)(lr >> 6) * 1024 + bx * 64 + (lr & 63);
            *(uint4*)&Bs[buf][lr][c * 4] =
                *(const uint4*)(B + grow * K + koff + c * 8);
        }
    };

    fill(0, 0);
    __syncthreads();

    const int gr = lane >> 2;
    const int gk = lane & 3;

    for (int t = 0; t < 32; t++) {
        const int cur = t & 1;
        if (t + 1 < 32) fill(cur ^ 1, (t + 1) * 32);
        // note: fill writes the OTHER buffer; barrier below protects reuse
#pragma unroll
        for (int k16 = 0; k16 < 2; k16++) {
            const int kb = k16 * 8;
            unsigned a[2][4], b[3][4][2];
#pragma unroll
            for (int mt = 0; mt < 2; mt++) {
                int m = wm * 32 + mt * 16 + gr;
                a[mt][0] = As[cur][m][kb + gk];
                a[mt][1] = As[cur][m + 8][kb + gk];
                a[mt][2] = As[cur][m][kb + gk + 4];
                a[mt][3] = As[cur][m + 8][kb + gk + 4];
            }
#pragma unroll
            for (int g = 0; g < 3; g++)
#pragma unroll
                for (int nt = 0; nt < 4; nt++) {
                    int n = g * 64 + wn * 32 + nt * 8 + gr;
                    b[g][nt][0] = Bs[cur][n][kb + gk];
                    b[g][nt][1] = Bs[cur][n][kb + gk + 4];
                }
#pragma unroll
            for (int mt = 0; mt < 2; mt++)
#pragma unroll
                for (int g = 0; g < 3; g++)
#pragma unroll
                    for (int nt = 0; nt < 4; nt++) {
                        asm volatile(
                            "mma.sync.aligned.m16n8k16.row.col.f32.f16.f16.f32 "
                            "{%0,%1,%2,%3}, {%4,%5,%6,%7}, {%8,%9}, {%0,%1,%2,%3};\n"
                            : "+f"(acc[mt][g][nt][0]), "+f"(acc[mt][g][nt][1]),
                              "+f"(acc[mt][g][nt][2]), "+f"(acc[mt][g][nt][3])
                            : "r"(a[mt][0]), "r"(a[mt][1]), "r"(a[mt][2]), "r"(a[mt][3]),
                              "r"(b[g][nt][0]), "r"(b[g][nt][1]));
                    }
        }
        __syncthreads();
    }

    // fused GRU epilogue
    const int gc2 = (lane & 3) * 2;
#pragma unroll
    for (int mt = 0; mt < 2; mt++) {
        long r0 = bm + wm * 32 + mt * 16 + gr;
#pragma unroll
        for (int nt = 0; nt < 4; nt++) {
            int h = bx * 64 + wn * 32 + nt * 8 + gc2;      // even
            float br0 = bhh[h],        br1 = bhh[h + 1];
            float bz0 = bhh[1024 + h], bz1 = bhh[1025 + h];
            float bn0 = bhh[2048 + h], bn1 = bhh[2049 + h];
#pragma unroll
            for (int p = 0; p < 2; p++) {
                long row = r0 + p * 8;
                const __half* gib = gi + row * G3 + h;
                __half2 gr2 = *(const __half2*)(gib);
                __half2 gz2 = *(const __half2*)(gib + 1024);
                __half2 gn2 = *(const __half2*)(gib + 2048);
                __half2 hp2 = *(const __half2*)(hp + row * HDIM + h);
                float ar = acc[mt][0][nt][2 * p],     ar1 = acc[mt][0][nt][2 * p + 1];
                float az = acc[mt][1][nt][2 * p],     az1 = acc[mt][1][nt][2 * p + 1];
                float an = acc[mt][2][nt][2 * p],     an1 = acc[mt][2][nt][2 * p + 1];
                float r_0 = sigmoidf(__low2float(gr2)  + ar  + br0);
                float r_1 = sigmoidf(__high2float(gr2) + ar1 + br1);
                float z_0 = sigmoidf(__low2float(gz2)  + az  + bz0);
                float z_1 = sigmoidf(__high2float(gz2) + az1 + bz1);
                float n_0 = tanhf(__low2float(gn2)  + r_0 * (an  + bn0));
                float n_1 = tanhf(__high2float(gn2) + r_1 * (an1 + bn1));
                float o0 = (1.f - z_0) * n_0 + z_0 * __low2float(hp2);
                float o1 = (1.f - z_1) * n_1 + z_1 * __high2float(hp2);
                *(__half2*)(out + row * HDIM + h) = __floats2half2_rn(o0, o1);
            }
        }
    }
}

// ---------------- fp16 mma.sync GEMM (msg / gi / output) ----------------
// act: 2 = split mu/std epilogue (f32), 3 = fp16 out.
#define BM 128
#define BN 128

__global__ __launch_bounds__(256, 2) void hgemm_nt(
    const __half* __restrict__ A, const __half* __restrict__ B,
    const float* __restrict__ bias, float* __restrict__ C,
    int N, int K, int act)
{
    __shared__ unsigned As[2][BM][KS];
    __shared__ unsigned Bs[2][BN][KS];

    const int tid  = threadIdx.x;
    const int lane = tid & 31;
    const int warp = tid >> 5;
    const int wm   = warp >> 1;
    const int wn   = warp & 1;
    const long bm  = (long)blockIdx.y * BM;
    const long bn  = (long)blockIdx.x * BN;

    const int lrow = tid >> 2;
    const int lcolh = (tid & 3) << 3;
    const int lcolu = (tid & 3) << 2;
    const __half* Aptr = A + (bm + lrow) * K + lcolh;
    const __half* Bptr = B + (bn + lrow) * K + lcolh;

    float acc[2][8][4];
#pragma unroll
    for (int i = 0; i < 2; i++)
#pragma unroll
        for (int j = 0; j < 8; j++)
#pragma unroll
            for (int q = 0; q < 4; q++) acc[i][j][q] = 0.f;

    {
#pragma unroll
        for (int r = 0; r < 2; r++) {
            *(uint4*)&As[0][lrow + r * 64][lcolu] =
                *(const uint4*)(Aptr + (long)(r * 64) * K);
            *(uint4*)&Bs[0][lrow + r * 64][lcolu] =
                *(const uint4*)(Bptr + (long)(r * 64) * K);
        }
    }
    __syncthreads();

    const int nt = K / 32;
    const int gr = lane >> 2;
    const int gk = lane & 3;
    uint4 pa[2], pb[2];

    for (int t = 0; t < nt; t++) {
        const int cur = t & 1, nxt = cur ^ 1;
        const bool more = (t + 1 < nt);
        if (more) {
            int koff = (t + 1) * 32;
#pragma unroll
            for (int r = 0; r < 2; r++) {
                pa[r] = *(const uint4*)(Aptr + (long)(r * 64) * K + koff);
                pb[r] = *(const uint4*)(Bptr + (long)(r * 64) * K + koff);
            }
        }
#pragma unroll
        for (int k16 = 0; k16 < 2; k16++) {
            const int kb = k16 * 8;
            unsigned a[2][4], b[8][2];
#pragma unroll
            for (int mt = 0; mt < 2; mt++) {
                int m = wm * 32 + mt * 16 + gr;
                a[mt][0] = As[cur][m][kb + gk];
                a[mt][1] = As[cur][m + 8][kb + gk];
                a[mt][2] = As[cur][m][kb + gk + 4];
                a[mt][3] = As[cur][m + 8][kb + gk + 4];
            }
#pragma unroll
            for (int ntile = 0; ntile < 8; ntile++) {
                int n = wn * 64 + ntile * 8 + gr;
                b[ntile][0] = Bs[cur][n][kb + gk];
                b[ntile][1] = Bs[cur][n][kb + gk + 4];
            }
#pragma unroll
            for (int mt = 0; mt < 2; mt++)
#pragma unroll
                for (int ntile = 0; ntile < 8; ntile++) {
                    asm volatile(
                        "mma.sync.aligned.m16n8k16.row.col.f32.f16.f16.f32 "
                        "{%0,%1,%2,%3}, {%4,%5,%6,%7}, {%8,%9}, {%0,%1,%2,%3};\n"
                        : "+f"(acc[mt][ntile][0]), "+f"(acc[mt][ntile][1]),
                          "+f"(acc[mt][ntile][2]), "+f"(acc[mt][ntile][3])
                        : "r"(a[mt][0]), "r"(a[mt][1]), "r"(a[mt][2]), "r"(a[mt][3]),
                          "r"(b[ntile][0]), "r"(b[ntile][1]));
                }
        }
        if (more) {
#pragma unroll
            for (int r = 0; r < 2; r++) {
                *(uint4*)&As[nxt][lrow + r * 64][lcolu] = pa[r];
                *(uint4*)&Bs[nxt][lrow + r * 64][lcolu] = pb[r];
            }
        }
        __syncthreads();
    }

    const int gc2 = (lane & 3) * 2;
#pragma unroll
    for (int mt = 0; mt < 2; mt++) {
        long row0 = bm + wm * 32 + mt * 16 + gr;
#pragma unroll
        for (int ntile = 0; ntile < 8; ntile++) {
            int col = bn + wn * 64 + ntile * 8 + gc2;
            float b0 = bias ? bias[col] : 0.f;
            float b1 = bias ? bias[col + 1] : 0.f;
            float2 v0, v1;
            v0.x = acc[mt][ntile][0] + b0; v0.y = acc[mt][ntile][1] + b1;
            v1.x = acc[mt][ntile][2] + b0; v1.y = acc[mt][ntile][3] + b1;
            if (act == 3) {
                __half* Ch = (__half*)C;
                *(__half2*)(Ch + row0 * N + col)       = __floats2half2_rn(v0.x, v0.y);
                *(__half2*)(Ch + (row0 + 8) * N + col) = __floats2half2_rn(v1.x, v1.y);
            } else if (act == 2) {
                float* dst;
                if (col < 256) {
                    dst = C + row0 * 256 + col;
                } else {
                    dst = C + 2048L * 256 + row0 * 256 + (col - 256);
                    v0.x = softplusf(v0.x); v0.y = softplusf(v0.y);
                    v1.x = softplusf(v1.x); v1.y = softplusf(v1.y);
                }
                *(float2*)dst             = v0;
                *(float2*)(dst + 8 * 256) = v1;
            } else {
                *(float2*)(C + row0 * N + col)       = v0;
                *(float2*)(C + (row0 + 8) * N + col) = v1;
            }
        }
    }
}

// ---------------- orchestration ----------------
extern "C" void kernel_launch(void* const* d_in, const int* in_sizes, int n_in,
                              void* d_out, int out_size)
{
    const float* X      = (const float*)d_in[0];
    const int*   adj    = (const int*)  d_in[1];
    const float* W_ih_c = (const float*)d_in[2];
    const float* W_hh_c = (const float*)d_in[3];
    const float* b_ih_c = (const float*)d_in[4];
    const float* b_hh_c = (const float*)d_in[5];
    const float* W_ih_l = (const float*)d_in[6];
    const float* W_hh_l = (const float*)d_in[7];
    const float* b_ih_l = (const float*)d_in[8];
    const float* b_hh_l = (const float*)d_in[9];
    const float* W_ih_r = (const float*)d_in[10];
    const float* W_hh_r = (const float*)d_in[11];
    const float* b_ih_r = (const float*)d_in[12];
    const float* b_hh_r = (const float*)d_in[13];
    const float* Wg     = (const float*)d_in[14];
    const float* bg     = (const float*)d_in[15];
    const float* Wm     = (const float*)d_in[16];
    const float* Wmu    = (const float*)d_in[17];
    const float* bmu    = (const float*)d_in[18];
    const float* Wstd   = (const float*)d_in[19];
    const float* bstd   = (const float*)d_in[20];

    float *bout;
    __half *msgAll, *giAll, *HinR, *Hv1, *Hv2, *Xpad, *Wx32, *Whh3R, *WmsgR, *WoutR;
    cudaGetSymbolAddress((void**)&bout,   g_bout);
    cudaGetSymbolAddress((void**)&msgAll, g_msgAll);
    cudaGetSymbolAddress((void**)&giAll,  g_giAll);
    cudaGetSymbolAddress((void**)&HinR,   g_HinR);
    cudaGetSymbolAddress((void**)&Hv1,    g_Hv1);
    cudaGetSymbolAddress((void**)&Hv2,    g_Hv2);
    cudaGetSymbolAddress((void**)&Xpad,   g_Xpad);
    cudaGetSymbolAddress((void**)&Wx32,   g_Wx32);
    cudaGetSymbolAddress((void**)&Whh3R,  g_Whh3R);
    cudaGetSymbolAddress((void**)&WmsgR,  g_WmsgR);
    cudaGetSymbolAddress((void**)&WoutR,  g_WoutR);

    __half* WhhcR = Whh3R;
    __half* WhhlR = Whh3R + (long)G3 * HDIM;
    __half* WhhrR = Whh3R + 2L * G3 * HDIM;

    cudaFuncSetAttribute(gru_gemm,
                         cudaFuncAttributeMaxDynamicSharedMemorySize, GG_SMEM);

    pack_xpad<<<(13 * BATCH * 32) / 256, 256>>>(X, adj, Xpad);
    pack_wx32<<<(G3 * 32) / 256, 256>>>(W_ih_c, Wx32,               27);
    pack_wx32<<<(G3 * 32) / 256, 256>>>(W_ih_l, Wx32 + (long)G3*32, 27);
    pack_wx32<<<(G3 * 32) / 256, 256>>>(W_ih_r, Wx32 + 2L*G3*32,    23);
    pack_msgw<<<(NMSG * HDIM) / 256, 256>>>(Wg, Wm, WmsgR);

    half_copy3<<<(3 * G3 * HDIM) / 256, 256>>>(W_hh_c, W_hh_l, W_hh_r,
                                               Whh3R, G3 * HDIM);
    half_copy2<<<(2 * 256 * HDIM) / 256, 256>>>(Wmu, Wstd, WoutR, 256 * HDIM);
    cudaMemcpyAsync(bout,       bmu,  256 * sizeof(float), cudaMemcpyDeviceToDevice, 0);
    cudaMemcpyAsync(bout + 256, bstd, 256 * sizeof(float), cudaMemcpyDeviceToDevice, 0);

    // gi projections (K=32 halves -> single K-tile), fp16 output (act=3)
    const long SEG = 6LL * BATCH;
    dim3 gGI6(G3 / BN, (6 * BATCH) / BM);
    dim3 gGI1(G3 / BN, BATCH / BM);
    hgemm_nt<<<gGI6, 256>>>(Xpad,                Wx32,               b_ih_c,
                            (float*)giAll,                  G3, 32, 3);
    hgemm_nt<<<gGI6, 256>>>(Xpad + SEG * 32,     Wx32 + (long)G3*32, b_ih_l,
                            (float*)(giAll + SEG * G3),     G3, 32, 3);
    hgemm_nt<<<gGI1, 256>>>(Xpad + 2 * SEG * 32, Wx32 + 2L*G3*32,    b_ih_r,
                            (float*)(giAll + 2 * SEG * G3), G3, 32, 3);

    dim3 gGRU(HDIM / 64, BATCH / 128);         // (16, 16)
    dim3 gMS(NMSG / BN, BATCH / BM);           // (32, 16)
    dim3 gOUT(512 / BN, BATCH / BM);           // (4, 16)
    const int EW = (BATCH * HDIM) / 256;       // 8192

    for (int v = 6; v >= 0; v--) {
        const __half* WhhR = (v == 0) ? WhhrR : WhhcR;
        const float* bhh   = (v == 0) ? b_hh_r : b_hh_c;
        const __half* gi1  = (v == 0) ? (giAll + 2 * SEG * G3)
                                      : (giAll + (long)(v - 1) * BATCH * G3);

        // GRU 1 -> Hv1
        if (v == 6) {
            gru_combine_bias<<<EW, 256>>>(gi1, bhh, Hv1);
        } else {
            msg_gather<<<EW, 256>>>(msgAll, adj, bg, HinR, v);
            gru_gemm<<<gGRU, 256, GG_SMEM>>>(HinR, WhhR, bhh, gi1, HinR, Hv1);
        }

        if (v > 0) {
            // GRU 2 (self-loop): Hv1 -> Hv2
            const __half* gi2 = giAll + (SEG + (long)(v - 1) * BATCH) * G3;
            gru_gemm<<<gGRU, 256, GG_SMEM>>>(Hv1, WhhlR, b_hh_l, gi2, Hv1, Hv2);

            // sender projections stored to msgAll plane v-1
            hgemm_nt<<<gMS, 256>>>(Hv2, WmsgR, nullptr,
                                   (float*)(msgAll + (long)(v - 1) * BATCH * NMSG),
                                   NMSG, HDIM, 3);
        }
    }

    // fused mu/std output GEMM (act=2 split epilogue); final hidden is Hv1 (v=0 GRU1)
    hgemm_nt<<<gOUT, 256>>>(Hv1, WoutR, bout, (float*)d_out, 512, HDIM, 2);
}